// round 1
// baseline (speedup 1.0000x reference)
#include <cuda_runtime.h>
#include <cstdint>

// ---------------------------------------------------------------------------
// Problem constants (fixed shapes from the reference)
// ---------------------------------------------------------------------------
static constexpr int B_WIN  = 2048;      // number of windows (B_)
static constexpr int NTOK   = 49;        // tokens per window
static constexpr int CDIM   = 384;       // channels
static constexpr int NHEAD  = 12;
static constexpr int DHEAD  = 32;
static constexpr int NW     = 64;        // mask windows
static constexpr int MROWS  = B_WIN * NTOK;   // 100352
static constexpr int QKVN   = 3 * CDIM;       // 1152

// Scratch (no cudaMalloc allowed) -------------------------------------------
__device__ float g_qkv[(size_t)MROWS * QKVN];   // (B_, N, 3, H, D) flattened
__device__ float g_att[(size_t)MROWS * CDIM];   // (B_, N, H, D) flattened

// ---------------------------------------------------------------------------
// GEMM: C[M,N] = A[M,K] @ B[N,K]^T + bias[N]   (both A,B row-major, K fast)
// Classic 128x128x16 register-blocked fp32 SGEMM, 256 threads, 8x8 microtile.
// All dims here divide the tiles exactly (M=100352, N in {1152,384}, K=384).
// ---------------------------------------------------------------------------
#define BM 128
#define BN 128
#define BKK 16
#define TM 8
#define TN 8

__global__ __launch_bounds__(256, 2)
void sgemm_tn_bias(const float* __restrict__ A,
                   const float* __restrict__ B,
                   const float* __restrict__ bias,
                   float* __restrict__ C,
                   int M, int N, int K)
{
    __shared__ float As[BKK][BM + 4];
    __shared__ float Bs[BKK][BN + 4];

    const int tid = threadIdx.x;
    const int m0  = blockIdx.y * BM;
    const int n0  = blockIdx.x * BN;

    const int tr = (tid / 16) * TM;   // row offset within tile
    const int tc = (tid % 16) * TN;   // col offset within tile

    float acc[TM][TN];
#pragma unroll
    for (int i = 0; i < TM; i++)
#pragma unroll
        for (int j = 0; j < TN; j++) acc[i][j] = 0.0f;

    for (int k0 = 0; k0 < K; k0 += BKK) {
        // Load A tile (BM x BKK) and B tile (BN x BKK), transposed into smem.
        // 128 rows * 4 float4 = 512 float4 loads per tile, 256 threads -> 2 each.
#pragma unroll
        for (int r = 0; r < 2; r++) {
            int idx = tid + r * 256;
            int row = idx >> 2;
            int c4  = (idx & 3) << 2;
            float4 va = *(const float4*)(A + (size_t)(m0 + row) * K + k0 + c4);
            As[c4 + 0][row] = va.x;
            As[c4 + 1][row] = va.y;
            As[c4 + 2][row] = va.z;
            As[c4 + 3][row] = va.w;
            float4 vb = *(const float4*)(B + (size_t)(n0 + row) * K + k0 + c4);
            Bs[c4 + 0][row] = vb.x;
            Bs[c4 + 1][row] = vb.y;
            Bs[c4 + 2][row] = vb.z;
            Bs[c4 + 3][row] = vb.w;
        }
        __syncthreads();

#pragma unroll
        for (int k = 0; k < BKK; k++) {
            float ar[TM], br[TN];
#pragma unroll
            for (int i = 0; i < TM; i++) ar[i] = As[k][tr + i];
#pragma unroll
            for (int j = 0; j < TN; j++) br[j] = Bs[k][tc + j];
#pragma unroll
            for (int i = 0; i < TM; i++)
#pragma unroll
                for (int j = 0; j < TN; j++)
                    acc[i][j] = fmaf(ar[i], br[j], acc[i][j]);
        }
        __syncthreads();
    }

    // Epilogue: add bias, vectorized store
#pragma unroll
    for (int i = 0; i < TM; i++) {
        float* crow = C + (size_t)(m0 + tr + i) * N + n0 + tc;
#pragma unroll
        for (int j4 = 0; j4 < TN; j4 += 4) {
            float4 v;
            v.x = acc[i][j4 + 0] + bias[n0 + tc + j4 + 0];
            v.y = acc[i][j4 + 1] + bias[n0 + tc + j4 + 1];
            v.z = acc[i][j4 + 2] + bias[n0 + tc + j4 + 2];
            v.w = acc[i][j4 + 3] + bias[n0 + tc + j4 + 3];
            *(float4*)(crow + j4) = v;
        }
    }
}

// ---------------------------------------------------------------------------
// Fused window attention: one block per (window b, head h).
//   S = scale * q k^T + rel_bias[h] + mask[b % 64]
//   P = softmax(S); O = P v  -> g_att in (b, n, h, d) layout
// ---------------------------------------------------------------------------
__global__ __launch_bounds__(256)
void attn_kernel(const float* __restrict__ qkv,       // (MROWS, 1152)
                 const float* __restrict__ mask,      // (64, 49, 49)
                 const float* __restrict__ bias_table,// (169, 12)
                 float* __restrict__ out)             // (MROWS, 384)
{
    const int b = blockIdx.x;   // 0..2047
    const int h = blockIdx.y;   // 0..11
    const int tid = threadIdx.x;
    const float scale = 0.17677669529663689f;  // 32^-0.5

    __shared__ float sQ[NTOK][DHEAD];        // q (pre-scaled)
    __shared__ float sKT[DHEAD][NTOK + 1];   // k transposed: [d][j]
    __shared__ float sV[NTOK][DHEAD];
    __shared__ float sS[NTOK][NTOK + 3];

    // Load q, k, v for this (b, h). qkv row = b*49+n, col = c3*384 + h*32 + d
    for (int idx = tid; idx < NTOK * DHEAD; idx += 256) {
        int n = idx >> 5;
        int d = idx & 31;
        const float* base = qkv + (size_t)(b * NTOK + n) * QKVN + h * DHEAD + d;
        sQ[n][d]  = base[0] * scale;
        sKT[d][n] = base[CDIM];
        sV[n][d]  = base[2 * CDIM];
    }
    __syncthreads();

    const int w = b & (NW - 1);
    const float* mrow = mask + (size_t)w * NTOK * NTOK;

    // S[i][j]
    for (int idx = tid; idx < NTOK * NTOK; idx += 256) {
        int i = idx / NTOK;
        int j = idx - i * NTOK;
        float s = 0.0f;
#pragma unroll
        for (int d = 0; d < DHEAD; d++)
            s = fmaf(sQ[i][d], sKT[d][j], s);
        int yi = i / 7, xi = i - yi * 7;
        int yj = j / 7, xj = j - yj * 7;
        int rel = (yi - yj + 6) * 13 + (xi - xj + 6);
        s += bias_table[rel * NHEAD + h] + mrow[i * NTOK + j];
        sS[i][j] = s;
    }
    __syncthreads();

    // Softmax per row (one thread per row; 49 rows)
    if (tid < NTOK) {
        float m = -1e30f;
#pragma unroll 7
        for (int j = 0; j < NTOK; j++) m = fmaxf(m, sS[tid][j]);
        float sum = 0.0f;
#pragma unroll 7
        for (int j = 0; j < NTOK; j++) {
            float e = __expf(sS[tid][j] - m);
            sS[tid][j] = e;
            sum += e;
        }
        float inv = 1.0f / sum;
#pragma unroll 7
        for (int j = 0; j < NTOK; j++) sS[tid][j] *= inv;
    }
    __syncthreads();

    // O = P @ V ;  write to (b, n, h, d)
    for (int idx = tid; idx < NTOK * DHEAD; idx += 256) {
        int i = idx >> 5;
        int d = idx & 31;
        float acc = 0.0f;
#pragma unroll
        for (int j = 0; j < NTOK; j++)
            acc = fmaf(sS[i][j], sV[j][d], acc);
        out[(size_t)(b * NTOK + i) * CDIM + h * DHEAD + d] = acc;
    }
}

// ---------------------------------------------------------------------------
// Launch
// inputs: 0=x (B_,N,C), 1=mask (64,49,49), 2=qkv_w (1152,384), 3=qkv_b (1152),
//         4=proj_w (384,384), 5=proj_b (384), 6=rel_bias_table (169,12)
// output: (B_, N, C) float32
// ---------------------------------------------------------------------------
extern "C" void kernel_launch(void* const* d_in, const int* in_sizes, int n_in,
                              void* d_out, int out_size)
{
    const float* x          = (const float*)d_in[0];
    const float* mask       = (const float*)d_in[1];
    const float* qkv_w      = (const float*)d_in[2];
    const float* qkv_b      = (const float*)d_in[3];
    const float* proj_w     = (const float*)d_in[4];
    const float* proj_b     = (const float*)d_in[5];
    const float* bias_table = (const float*)d_in[6];
    float* out = (float*)d_out;

    float* qkv;
    float* att;
    cudaGetSymbolAddress((void**)&qkv, g_qkv);
    cudaGetSymbolAddress((void**)&att, g_att);

    // 1) QKV projection: (100352,384) @ (1152,384)^T + b -> (100352,1152)
    {
        dim3 grid(QKVN / BN, MROWS / BM);
        sgemm_tn_bias<<<grid, 256>>>(x, qkv_w, qkv_b, qkv, MROWS, QKVN, CDIM);
    }

    // 2) Fused windowed attention
    {
        dim3 grid(B_WIN, NHEAD);
        attn_kernel<<<grid, 256>>>(qkv, mask, bias_table, att);
    }

    // 3) Output projection: (100352,384) @ (384,384)^T + b -> out
    {
        dim3 grid(CDIM / BN, MROWS / BM);
        sgemm_tn_bias<<<grid, 256>>>(att, proj_w, proj_b, out, MROWS, CDIM, CDIM);
    }
}

// round 2
// speedup vs baseline: 1.8870x; 1.8870x over previous
#include <cuda_runtime.h>
#include <cstdint>

// ---------------------------------------------------------------------------
// Problem constants
// ---------------------------------------------------------------------------
static constexpr int B_WIN  = 2048;
static constexpr int NTOK   = 49;
static constexpr int CDIM   = 384;
static constexpr int NHEAD  = 12;
static constexpr int DHEAD  = 32;
static constexpr int NW     = 64;
static constexpr int MROWS  = B_WIN * NTOK;   // 100352
static constexpr int QKVN   = 3 * CDIM;       // 1152

// Scratch (no cudaMalloc allowed)
__device__ float g_qkv[(size_t)MROWS * QKVN];
__device__ float g_att[(size_t)MROWS * CDIM];

// ---------------------------------------------------------------------------
// TF32 tensor-core GEMM:  C[M,N] = A[M,K] @ B[N,K]^T + bias[N]
// Block tile 256x128, 8 warps (64x64 per warp), BK=16, 3-stage cp.async.
// Requires M % 256 == 0, N % 128 == 0, K % 16 == 0 (true for our shapes).
// ---------------------------------------------------------------------------
#define GBM 256
#define GBN 128
#define GBK 16
#define ROWSTRIDE 20              // 16 k-floats + 4 pad (conflict-free frags)
#define A_FLOATS (GBM * ROWSTRIDE)   // 5120
#define B_FLOATS (GBN * ROWSTRIDE)   // 2560
#define BUF_FLOATS (A_FLOATS + B_FLOATS)  // 7680
#define NSTAGE 3
#define SMEM_BYTES (NSTAGE * BUF_FLOATS * 4)  // 92160

__device__ __forceinline__ void cp_async16(void* smem_dst, const void* gmem_src) {
    uint32_t s = (uint32_t)__cvta_generic_to_shared(smem_dst);
    asm volatile("cp.async.cg.shared.global [%0], [%1], 16;\n" :: "r"(s), "l"(gmem_src));
}
__device__ __forceinline__ void cp_commit() { asm volatile("cp.async.commit_group;\n"); }
template<int N> __device__ __forceinline__ void cp_wait() {
    asm volatile("cp.async.wait_group %0;\n" :: "n"(N));
}
__device__ __forceinline__ uint32_t f2tf32(float x) {
    uint32_t r;
    asm("cvt.rna.tf32.f32 %0, %1;\n" : "=r"(r) : "f"(x));
    return r;
}
__device__ __forceinline__ void mma_tf32(float* c, const uint32_t* a, const uint32_t* b) {
    asm volatile(
        "mma.sync.aligned.m16n8k8.row.col.f32.tf32.tf32.f32 "
        "{%0,%1,%2,%3}, {%4,%5,%6,%7}, {%8,%9}, {%0,%1,%2,%3};\n"
        : "+f"(c[0]), "+f"(c[1]), "+f"(c[2]), "+f"(c[3])
        : "r"(a[0]), "r"(a[1]), "r"(a[2]), "r"(a[3]), "r"(b[0]), "r"(b[1]));
}

__global__ __launch_bounds__(256, 1)
void gemm_tf32_tn_bias(const float* __restrict__ A,
                       const float* __restrict__ B,
                       const float* __restrict__ bias,
                       float* __restrict__ C,
                       int M, int N, int K)
{
    extern __shared__ float smem[];

    const int tid  = threadIdx.x;
    const int wid  = tid >> 5;
    const int lane = tid & 31;
    const int g    = lane >> 2;     // groupID 0..7
    const int tig  = lane & 3;      // thread-in-group 0..3

    const int m0 = blockIdx.y * GBM;
    const int n0 = blockIdx.x * GBN;
    const int warp_m = wid >> 1;    // 0..3 -> 64-row slab
    const int warp_n = wid & 1;     // 0..1 -> 64-col slab

    const int KT = K / GBK;

    float acc[4][8][4];
#pragma unroll
    for (int mt = 0; mt < 4; mt++)
#pragma unroll
        for (int nt = 0; nt < 8; nt++)
#pragma unroll
            for (int r = 0; r < 4; r++) acc[mt][nt][r] = 0.0f;

    // ---- tile loader (cp.async) ----
    auto load_tile = [&](int kt, int buf) {
        float* As = smem + buf * BUF_FLOATS;
        float* Bs = As + A_FLOATS;
        const int k0 = kt * GBK;
#pragma unroll
        for (int j = 0; j < 4; j++) {             // A: 256 rows x 4 chunks
            int idx = j * 256 + tid;
            int row = idx >> 2;
            int c4  = (idx & 3) << 2;
            cp_async16(As + row * ROWSTRIDE + c4,
                       A + (size_t)(m0 + row) * K + k0 + c4);
        }
#pragma unroll
        for (int j = 0; j < 2; j++) {             // B: 128 rows x 4 chunks
            int idx = j * 256 + tid;
            int row = idx >> 2;
            int c4  = (idx & 3) << 2;
            cp_async16(Bs + row * ROWSTRIDE + c4,
                       B + (size_t)(n0 + row) * K + k0 + c4);
        }
    };

    // prologue: stage 0 and 1
    load_tile(0, 0); cp_commit();
    load_tile(1, 1); cp_commit();

    for (int kt = 0; kt < KT; kt++) {
        if (kt + 2 < KT) load_tile(kt + 2, (kt + 2) % NSTAGE);
        cp_commit();                 // empty group when no loads -> uniform wait
        cp_wait<2>();
        __syncthreads();

        const float* As = smem + (kt % NSTAGE) * BUF_FLOATS;
        const float* Bs = As + A_FLOATS;

#pragma unroll
        for (int ks = 0; ks < 2; ks++) {
            const int k0 = ks * 8;
            uint32_t af[4][4];
            uint32_t bf[8][2];
#pragma unroll
            for (int mt = 0; mt < 4; mt++) {
                int r = warp_m * 64 + mt * 16 + g;
                af[mt][0] = f2tf32(As[(r    ) * ROWSTRIDE + k0 + tig    ]);
                af[mt][1] = f2tf32(As[(r + 8) * ROWSTRIDE + k0 + tig    ]);
                af[mt][2] = f2tf32(As[(r    ) * ROWSTRIDE + k0 + tig + 4]);
                af[mt][3] = f2tf32(As[(r + 8) * ROWSTRIDE + k0 + tig + 4]);
            }
#pragma unroll
            for (int nt = 0; nt < 8; nt++) {
                int n = warp_n * 64 + nt * 8 + g;
                bf[nt][0] = f2tf32(Bs[n * ROWSTRIDE + k0 + tig    ]);
                bf[nt][1] = f2tf32(Bs[n * ROWSTRIDE + k0 + tig + 4]);
            }
#pragma unroll
            for (int mt = 0; mt < 4; mt++)
#pragma unroll
                for (int nt = 0; nt < 8; nt++)
                    mma_tf32(acc[mt][nt], af[mt], bf[nt]);
        }
        __syncthreads();
    }

    // ---- epilogue: bias + store (float2) ----
#pragma unroll
    for (int mt = 0; mt < 4; mt++) {
        int r0 = m0 + warp_m * 64 + mt * 16 + g;
#pragma unroll
        for (int nt = 0; nt < 8; nt++) {
            int c = n0 + warp_n * 64 + nt * 8 + tig * 2;
            float b0 = bias[c];
            float b1 = bias[c + 1];
            float2 v0 = make_float2(acc[mt][nt][0] + b0, acc[mt][nt][1] + b1);
            float2 v1 = make_float2(acc[mt][nt][2] + b0, acc[mt][nt][3] + b1);
            *(float2*)(C + (size_t)r0 * N + c)       = v0;
            *(float2*)(C + (size_t)(r0 + 8) * N + c) = v1;
        }
    }
}

// ---------------------------------------------------------------------------
// Fused window attention (unchanged from R1): one block per (window, head)
// ---------------------------------------------------------------------------
__global__ __launch_bounds__(256)
void attn_kernel(const float* __restrict__ qkv,
                 const float* __restrict__ mask,
                 const float* __restrict__ bias_table,
                 float* __restrict__ out)
{
    const int b = blockIdx.x;
    const int h = blockIdx.y;
    const int tid = threadIdx.x;
    const float scale = 0.17677669529663689f;

    __shared__ float sQ[NTOK][DHEAD];
    __shared__ float sKT[DHEAD][NTOK + 1];
    __shared__ float sV[NTOK][DHEAD];
    __shared__ float sS[NTOK][NTOK + 3];

    for (int idx = tid; idx < NTOK * DHEAD; idx += 256) {
        int n = idx >> 5;
        int d = idx & 31;
        const float* base = qkv + (size_t)(b * NTOK + n) * QKVN + h * DHEAD + d;
        sQ[n][d]  = base[0] * scale;
        sKT[d][n] = base[CDIM];
        sV[n][d]  = base[2 * CDIM];
    }
    __syncthreads();

    const int w = b & (NW - 1);
    const float* mrow = mask + (size_t)w * NTOK * NTOK;

    for (int idx = tid; idx < NTOK * NTOK; idx += 256) {
        int i = idx / NTOK;
        int j = idx - i * NTOK;
        float s = 0.0f;
#pragma unroll
        for (int d = 0; d < DHEAD; d++)
            s = fmaf(sQ[i][d], sKT[d][j], s);
        int yi = i / 7, xi = i - yi * 7;
        int yj = j / 7, xj = j - yj * 7;
        int rel = (yi - yj + 6) * 13 + (xi - xj + 6);
        s += bias_table[rel * NHEAD + h] + mrow[i * NTOK + j];
        sS[i][j] = s;
    }
    __syncthreads();

    if (tid < NTOK) {
        float m = -1e30f;
#pragma unroll 7
        for (int j = 0; j < NTOK; j++) m = fmaxf(m, sS[tid][j]);
        float sum = 0.0f;
#pragma unroll 7
        for (int j = 0; j < NTOK; j++) {
            float e = __expf(sS[tid][j] - m);
            sS[tid][j] = e;
            sum += e;
        }
        float inv = 1.0f / sum;
#pragma unroll 7
        for (int j = 0; j < NTOK; j++) sS[tid][j] *= inv;
    }
    __syncthreads();

    for (int idx = tid; idx < NTOK * DHEAD; idx += 256) {
        int i = idx >> 5;
        int d = idx & 31;
        float acc = 0.0f;
#pragma unroll
        for (int j = 0; j < NTOK; j++)
            acc = fmaf(sS[i][j], sV[j][d], acc);
        out[(size_t)(b * NTOK + i) * CDIM + h * DHEAD + d] = acc;
    }
}

// ---------------------------------------------------------------------------
// Launch
// ---------------------------------------------------------------------------
extern "C" void kernel_launch(void* const* d_in, const int* in_sizes, int n_in,
                              void* d_out, int out_size)
{
    const float* x          = (const float*)d_in[0];
    const float* mask       = (const float*)d_in[1];
    const float* qkv_w      = (const float*)d_in[2];
    const float* qkv_b      = (const float*)d_in[3];
    const float* proj_w     = (const float*)d_in[4];
    const float* proj_b     = (const float*)d_in[5];
    const float* bias_table = (const float*)d_in[6];
    float* out = (float*)d_out;

    float* qkv;
    float* att;
    cudaGetSymbolAddress((void**)&qkv, g_qkv);
    cudaGetSymbolAddress((void**)&att, g_att);

    static bool attr_set = false;
    if (!attr_set) {
        cudaFuncSetAttribute(gemm_tf32_tn_bias,
                             cudaFuncAttributeMaxDynamicSharedMemorySize,
                             SMEM_BYTES);
        attr_set = true;
    }

    // 1) QKV projection: (100352,384) @ (1152,384)^T + b -> (100352,1152)
    {
        dim3 grid(QKVN / GBN, MROWS / GBM);   // (9, 392)
        gemm_tf32_tn_bias<<<grid, 256, SMEM_BYTES>>>(x, qkv_w, qkv_b, qkv,
                                                     MROWS, QKVN, CDIM);
    }

    // 2) Fused windowed attention
    {
        dim3 grid(B_WIN, NHEAD);
        attn_kernel<<<grid, 256>>>(qkv, mask, bias_table, att);
    }

    // 3) Output projection: (100352,384) @ (384,384)^T + b -> out
    {
        dim3 grid(CDIM / GBN, MROWS / GBM);   // (3, 392)
        gemm_tf32_tn_bias<<<grid, 256, SMEM_BYTES>>>(att, proj_w, proj_b, out,
                                                     MROWS, CDIM, CDIM);
    }
}

// round 3
// speedup vs baseline: 1.9519x; 1.0344x over previous
#include <cuda_runtime.h>
#include <cstdint>

// ---------------------------------------------------------------------------
// Problem constants
// ---------------------------------------------------------------------------
static constexpr int B_WIN  = 2048;
static constexpr int NTOK   = 49;
static constexpr int CDIM   = 384;
static constexpr int NHEAD  = 12;
static constexpr int DHEAD  = 32;
static constexpr int NW     = 64;
static constexpr int MROWS  = B_WIN * NTOK;   // 100352
static constexpr int QKVN   = 3 * CDIM;       // 1152

// Scratch (no cudaMalloc allowed)
__device__ float g_qkv[(size_t)MROWS * QKVN];
__device__ float g_att[(size_t)MROWS * CDIM];

// ---------------------------------------------------------------------------
// TF32 tensor-core GEMM:  C[M,N] = A[M,K] @ B[N,K]^T + bias[N]
// Block tile 128x128, 8 warps (warp tile 64x32), BK=16, 3-stage cp.async.
// __launch_bounds__(256,2) caps regs at 128 -> 2 CTAs (16 warps) per SM.
// ---------------------------------------------------------------------------
#define GBM 128
#define GBN 128
#define GBK 16
#define ROWSTRIDE 20                    // 16 k-floats + 4 pad
#define A_FLOATS (GBM * ROWSTRIDE)      // 2560
#define B_FLOATS (GBN * ROWSTRIDE)      // 2560
#define BUF_FLOATS (A_FLOATS + B_FLOATS)
#define NSTAGE 3
#define SMEM_BYTES (NSTAGE * BUF_FLOATS * 4)   // 61440

__device__ __forceinline__ void cp_async16(void* smem_dst, const void* gmem_src) {
    uint32_t s = (uint32_t)__cvta_generic_to_shared(smem_dst);
    asm volatile("cp.async.cg.shared.global [%0], [%1], 16;\n" :: "r"(s), "l"(gmem_src));
}
__device__ __forceinline__ void cp_commit() { asm volatile("cp.async.commit_group;\n"); }
template<int N> __device__ __forceinline__ void cp_wait() {
    asm volatile("cp.async.wait_group %0;\n" :: "n"(N));
}
__device__ __forceinline__ uint32_t f2tf32(float x) {
    uint32_t r;
    asm("cvt.rna.tf32.f32 %0, %1;\n" : "=r"(r) : "f"(x));
    return r;
}
__device__ __forceinline__ void mma_tf32(float* c, const uint32_t* a, const uint32_t* b) {
    asm volatile(
        "mma.sync.aligned.m16n8k8.row.col.f32.tf32.tf32.f32 "
        "{%0,%1,%2,%3}, {%4,%5,%6,%7}, {%8,%9}, {%0,%1,%2,%3};\n"
        : "+f"(c[0]), "+f"(c[1]), "+f"(c[2]), "+f"(c[3])
        : "r"(a[0]), "r"(a[1]), "r"(a[2]), "r"(a[3]), "r"(b[0]), "r"(b[1]));
}

__global__ __launch_bounds__(256, 2)
void gemm_tf32_tn_bias(const float* __restrict__ A,
                       const float* __restrict__ B,
                       const float* __restrict__ bias,
                       float* __restrict__ C,
                       int M, int N, int K)
{
    extern __shared__ float smem[];

    const int tid  = threadIdx.x;
    const int wid  = tid >> 5;
    const int lane = tid & 31;
    const int g    = lane >> 2;
    const int tig  = lane & 3;

    const int m0 = blockIdx.y * GBM;
    const int n0 = blockIdx.x * GBN;
    const int warp_m = wid >> 2;    // 0..1  -> 64-row slab
    const int warp_n = wid & 3;     // 0..3  -> 32-col slab

    const int KT = K / GBK;

    float acc[4][4][4];
#pragma unroll
    for (int mt = 0; mt < 4; mt++)
#pragma unroll
        for (int nt = 0; nt < 4; nt++)
#pragma unroll
            for (int r = 0; r < 4; r++) acc[mt][nt][r] = 0.0f;

    auto load_tile = [&](int kt, int buf) {
        float* As = smem + buf * BUF_FLOATS;
        float* Bs = As + A_FLOATS;
        const int k0 = kt * GBK;
#pragma unroll
        for (int j = 0; j < 2; j++) {              // A: 128 rows x 4 chunks
            int idx = j * 256 + tid;
            int row = idx >> 2;
            int c4  = (idx & 3) << 2;
            cp_async16(As + row * ROWSTRIDE + c4,
                       A + (size_t)(m0 + row) * K + k0 + c4);
        }
#pragma unroll
        for (int j = 0; j < 2; j++) {              // B: 128 rows x 4 chunks
            int idx = j * 256 + tid;
            int row = idx >> 2;
            int c4  = (idx & 3) << 2;
            cp_async16(Bs + row * ROWSTRIDE + c4,
                       B + (size_t)(n0 + row) * K + k0 + c4);
        }
    };

    load_tile(0, 0); cp_commit();
    load_tile(1, 1); cp_commit();

    for (int kt = 0; kt < KT; kt++) {
        if (kt + 2 < KT) load_tile(kt + 2, (kt + 2) % NSTAGE);
        cp_commit();
        cp_wait<2>();
        __syncthreads();

        const float* As = smem + (kt % NSTAGE) * BUF_FLOATS;
        const float* Bs = As + A_FLOATS;

#pragma unroll
        for (int ks = 0; ks < 2; ks++) {
            const int k0 = ks * 8;
            uint32_t af[4][4];
            uint32_t bf[4][2];
#pragma unroll
            for (int mt = 0; mt < 4; mt++) {
                int r = warp_m * 64 + mt * 16 + g;
                af[mt][0] = f2tf32(As[(r    ) * ROWSTRIDE + k0 + tig    ]);
                af[mt][1] = f2tf32(As[(r + 8) * ROWSTRIDE + k0 + tig    ]);
                af[mt][2] = f2tf32(As[(r    ) * ROWSTRIDE + k0 + tig + 4]);
                af[mt][3] = f2tf32(As[(r + 8) * ROWSTRIDE + k0 + tig + 4]);
            }
#pragma unroll
            for (int nt = 0; nt < 4; nt++) {
                int n = warp_n * 32 + nt * 8 + g;
                bf[nt][0] = f2tf32(Bs[n * ROWSTRIDE + k0 + tig    ]);
                bf[nt][1] = f2tf32(Bs[n * ROWSTRIDE + k0 + tig + 4]);
            }
#pragma unroll
            for (int mt = 0; mt < 4; mt++)
#pragma unroll
                for (int nt = 0; nt < 4; nt++)
                    mma_tf32(acc[mt][nt], af[mt], bf[nt]);
        }
        __syncthreads();
    }

#pragma unroll
    for (int mt = 0; mt < 4; mt++) {
        int r0 = m0 + warp_m * 64 + mt * 16 + g;
#pragma unroll
        for (int nt = 0; nt < 4; nt++) {
            int c = n0 + warp_n * 32 + nt * 8 + tig * 2;
            float b0 = bias[c];
            float b1 = bias[c + 1];
            float2 v0 = make_float2(acc[mt][nt][0] + b0, acc[mt][nt][1] + b1);
            float2 v1 = make_float2(acc[mt][nt][2] + b0, acc[mt][nt][3] + b1);
            *(float2*)(C + (size_t)r0 * N + c)       = v0;
            *(float2*)(C + (size_t)(r0 + 8) * N + c) = v1;
        }
    }
}

// ---------------------------------------------------------------------------
// Fused window attention, vectorized: one block (128 thr) per (window, head).
// S-phase: float4 over j (K^T padded to 52 cols); PV: float4 over d.
// ---------------------------------------------------------------------------
static constexpr int JPAD = 52;   // 49 padded; 52*4B = 208B rows, 16B aligned

__global__ __launch_bounds__(128)
void attn_kernel(const float* __restrict__ qkv,
                 const float* __restrict__ mask,
                 const float* __restrict__ bias_table,
                 float* __restrict__ out)
{
    const int b = blockIdx.x;
    const int h = blockIdx.y;
    const int tid = threadIdx.x;
    const float scale = 0.17677669529663689f;

    __shared__ float sQ[NTOK][DHEAD];
    __shared__ float sKT[DHEAD][JPAD];
    __shared__ float sV[NTOK][DHEAD];
    __shared__ float sS[NTOK][JPAD];

    // Load q (pre-scaled), k (transposed), v
    for (int idx = tid; idx < NTOK * DHEAD; idx += 128) {
        int n = idx >> 5;
        int d = idx & 31;
        const float* base = qkv + (size_t)(b * NTOK + n) * QKVN + h * DHEAD + d;
        sQ[n][d]  = base[0] * scale;
        sKT[d][n] = base[CDIM];
        sV[n][d]  = base[2 * CDIM];
    }
    // Zero the KT padding columns (j = 49..51)
    if (tid < DHEAD * 3) {
        int d = tid / 3;
        int j = NTOK + tid % 3;
        sKT[d][j] = 0.0f;
    }
    __syncthreads();

    const int w = b & (NW - 1);
    const float* mrow = mask + (size_t)w * NTOK * NTOK;

    // S[i][j4..j4+3] = q_i . k_j + bias + mask
    for (int item = tid; item < NTOK * (JPAD / 4); item += 128) {
        int i  = item / (JPAD / 4);
        int j4 = (item - i * (JPAD / 4)) * 4;
        float4 acc = make_float4(0.f, 0.f, 0.f, 0.f);
#pragma unroll
        for (int d = 0; d < DHEAD; d++) {
            float q = sQ[i][d];
            float4 kv = *(const float4*)&sKT[d][j4];
            acc.x = fmaf(q, kv.x, acc.x);
            acc.y = fmaf(q, kv.y, acc.y);
            acc.z = fmaf(q, kv.z, acc.z);
            acc.w = fmaf(q, kv.w, acc.w);
        }
        int yi = i / 7, xi = i - yi * 7;
        float r[4] = {acc.x, acc.y, acc.z, acc.w};
#pragma unroll
        for (int u = 0; u < 4; u++) {
            int j = j4 + u;
            if (j < NTOK) {
                int yj = j / 7, xj = j - yj * 7;
                int rel = (yi - yj + 6) * 13 + (xi - xj + 6);
                r[u] += bias_table[rel * NHEAD + h] + mrow[i * NTOK + j];
            }
        }
        *(float4*)&sS[i][j4] = make_float4(r[0], r[1], r[2], r[3]);
    }
    __syncthreads();

    // Row softmax (one thread per row)
    if (tid < NTOK) {
        float m = -1e30f;
#pragma unroll 7
        for (int j = 0; j < NTOK; j++) m = fmaxf(m, sS[tid][j]);
        float sum = 0.0f;
#pragma unroll 7
        for (int j = 0; j < NTOK; j++) {
            float e = __expf(sS[tid][j] - m);
            sS[tid][j] = e;
            sum += e;
        }
        float inv = 1.0f / sum;
#pragma unroll 7
        for (int j = 0; j < NTOK; j++) sS[tid][j] *= inv;
    }
    __syncthreads();

    // O[i][d4..d4+3] = sum_j P[i][j] * V[j][d4..]
    for (int item = tid; item < NTOK * (DHEAD / 4); item += 128) {
        int i  = item / (DHEAD / 4);
        int d4 = (item - i * (DHEAD / 4)) * 4;
        float4 acc = make_float4(0.f, 0.f, 0.f, 0.f);
#pragma unroll 7
        for (int j = 0; j < NTOK; j++) {
            float p = sS[i][j];
            float4 v = *(const float4*)&sV[j][d4];
            acc.x = fmaf(p, v.x, acc.x);
            acc.y = fmaf(p, v.y, acc.y);
            acc.z = fmaf(p, v.z, acc.z);
            acc.w = fmaf(p, v.w, acc.w);
        }
        *(float4*)(out + (size_t)(b * NTOK + i) * CDIM + h * DHEAD + d4) = acc;
    }
}

// ---------------------------------------------------------------------------
// Launch
// ---------------------------------------------------------------------------
extern "C" void kernel_launch(void* const* d_in, const int* in_sizes, int n_in,
                              void* d_out, int out_size)
{
    const float* x          = (const float*)d_in[0];
    const float* mask       = (const float*)d_in[1];
    const float* qkv_w      = (const float*)d_in[2];
    const float* qkv_b      = (const float*)d_in[3];
    const float* proj_w     = (const float*)d_in[4];
    const float* proj_b     = (const float*)d_in[5];
    const float* bias_table = (const float*)d_in[6];
    float* out = (float*)d_out;

    float* qkv;
    float* att;
    cudaGetSymbolAddress((void**)&qkv, g_qkv);
    cudaGetSymbolAddress((void**)&att, g_att);

    static bool attr_set = false;
    if (!attr_set) {
        cudaFuncSetAttribute(gemm_tf32_tn_bias,
                             cudaFuncAttributeMaxDynamicSharedMemorySize,
                             SMEM_BYTES);
        attr_set = true;
    }

    // 1) QKV projection: (100352,384) @ (1152,384)^T + b -> (100352,1152)
    {
        dim3 grid(QKVN / GBN, MROWS / GBM);   // (9, 784)
        gemm_tf32_tn_bias<<<grid, 256, SMEM_BYTES>>>(x, qkv_w, qkv_b, qkv,
                                                     MROWS, QKVN, CDIM);
    }

    // 2) Fused windowed attention
    {
        dim3 grid(B_WIN, NHEAD);
        attn_kernel<<<grid, 128>>>(qkv, mask, bias_table, att);
    }

    // 3) Output projection: (100352,384) @ (384,384)^T + b -> out
    {
        dim3 grid(CDIM / GBN, MROWS / GBM);   // (3, 784)
        gemm_tf32_tn_bias<<<grid, 256, SMEM_BYTES>>>(att, proj_w, proj_b, out,
                                                     MROWS, CDIM, CDIM);
    }
}

// round 7
// speedup vs baseline: 2.4908x; 1.2761x over previous
#include <cuda_runtime.h>
#include <cstdint>

// ---------------------------------------------------------------------------
// Problem constants
// ---------------------------------------------------------------------------
static constexpr int B_WIN  = 2048;
static constexpr int NTOK   = 49;
static constexpr int CDIM   = 384;
static constexpr int NHEAD  = 12;
static constexpr int DHEAD  = 32;
static constexpr int NW     = 64;
static constexpr int MROWS  = B_WIN * NTOK;   // 100352
static constexpr int QKVN   = 3 * CDIM;       // 1152

// Scratch (no cudaMalloc allowed)
__device__ float g_qkv[(size_t)MROWS * QKVN];
__device__ float g_att[(size_t)MROWS * CDIM];

// ---------------------------------------------------------------------------
// Common MMA helpers (m16n8k8 tf32)
// ---------------------------------------------------------------------------
__device__ __forceinline__ void cp_async16(void* smem_dst, const void* gmem_src) {
    uint32_t s = (uint32_t)__cvta_generic_to_shared(smem_dst);
    asm volatile("cp.async.cg.shared.global [%0], [%1], 16;\n" :: "r"(s), "l"(gmem_src));
}
__device__ __forceinline__ void cp_commit() { asm volatile("cp.async.commit_group;\n"); }
template<int N> __device__ __forceinline__ void cp_wait() {
    asm volatile("cp.async.wait_group %0;\n" :: "n"(N));
}
__device__ __forceinline__ uint32_t f2tf32(float x) {
    uint32_t r;
    asm("cvt.rna.tf32.f32 %0, %1;\n" : "=r"(r) : "f"(x));
    return r;
}
__device__ __forceinline__ void mma_tf32(float* c, const uint32_t* a, const uint32_t* b) {
    asm volatile(
        "mma.sync.aligned.m16n8k8.row.col.f32.tf32.tf32.f32 "
        "{%0,%1,%2,%3}, {%4,%5,%6,%7}, {%8,%9}, {%0,%1,%2,%3};\n"
        : "+f"(c[0]), "+f"(c[1]), "+f"(c[2]), "+f"(c[3])
        : "r"(a[0]), "r"(a[1]), "r"(a[2]), "r"(a[3]), "r"(b[0]), "r"(b[1]));
}
__device__ __forceinline__ uint32_t fbits(float x) { return __float_as_uint(x); }

// ---------------------------------------------------------------------------
// TF32 GEMM:  C[M,N] = A[M,K] @ B[N,K]^T + bias[N]   (unchanged, proven)
// ---------------------------------------------------------------------------
#define GBM 128
#define GBN 128
#define GBK 16
#define ROWSTRIDE 20
#define A_FLOATS (GBM * ROWSTRIDE)
#define B_FLOATS (GBN * ROWSTRIDE)
#define BUF_FLOATS (A_FLOATS + B_FLOATS)
#define NSTAGE 3
#define SMEM_BYTES (NSTAGE * BUF_FLOATS * 4)   // 61440

__global__ __launch_bounds__(256, 2)
void gemm_tf32_tn_bias(const float* __restrict__ A,
                       const float* __restrict__ B,
                       const float* __restrict__ bias,
                       float* __restrict__ C,
                       int M, int N, int K)
{
    extern __shared__ float smem[];

    const int tid  = threadIdx.x;
    const int wid  = tid >> 5;
    const int lane = tid & 31;
    const int g    = lane >> 2;
    const int tig  = lane & 3;

    const int m0 = blockIdx.y * GBM;
    const int n0 = blockIdx.x * GBN;
    const int warp_m = wid >> 2;
    const int warp_n = wid & 3;

    const int KT = K / GBK;

    float acc[4][4][4];
#pragma unroll
    for (int mt = 0; mt < 4; mt++)
#pragma unroll
        for (int nt = 0; nt < 4; nt++)
#pragma unroll
            for (int r = 0; r < 4; r++) acc[mt][nt][r] = 0.0f;

    auto load_tile = [&](int kt, int buf) {
        float* As = smem + buf * BUF_FLOATS;
        float* Bs = As + A_FLOATS;
        const int k0 = kt * GBK;
#pragma unroll
        for (int j = 0; j < 2; j++) {
            int idx = j * 256 + tid;
            int row = idx >> 2;
            int c4  = (idx & 3) << 2;
            cp_async16(As + row * ROWSTRIDE + c4,
                       A + (size_t)(m0 + row) * K + k0 + c4);
        }
#pragma unroll
        for (int j = 0; j < 2; j++) {
            int idx = j * 256 + tid;
            int row = idx >> 2;
            int c4  = (idx & 3) << 2;
            cp_async16(Bs + row * ROWSTRIDE + c4,
                       B + (size_t)(n0 + row) * K + k0 + c4);
        }
    };

    load_tile(0, 0); cp_commit();
    load_tile(1, 1); cp_commit();

    for (int kt = 0; kt < KT; kt++) {
        if (kt + 2 < KT) load_tile(kt + 2, (kt + 2) % NSTAGE);
        cp_commit();
        cp_wait<2>();
        __syncthreads();

        const float* As = smem + (kt % NSTAGE) * BUF_FLOATS;
        const float* Bs = As + A_FLOATS;

#pragma unroll
        for (int ks = 0; ks < 2; ks++) {
            const int k0 = ks * 8;
            uint32_t af[4][4];
            uint32_t bf[4][2];
#pragma unroll
            for (int mt = 0; mt < 4; mt++) {
                int r = warp_m * 64 + mt * 16 + g;
                af[mt][0] = f2tf32(As[(r    ) * ROWSTRIDE + k0 + tig    ]);
                af[mt][1] = f2tf32(As[(r + 8) * ROWSTRIDE + k0 + tig    ]);
                af[mt][2] = f2tf32(As[(r    ) * ROWSTRIDE + k0 + tig + 4]);
                af[mt][3] = f2tf32(As[(r + 8) * ROWSTRIDE + k0 + tig + 4]);
            }
#pragma unroll
            for (int nt = 0; nt < 4; nt++) {
                int n = warp_n * 32 + nt * 8 + g;
                bf[nt][0] = f2tf32(Bs[n * ROWSTRIDE + k0 + tig    ]);
                bf[nt][1] = f2tf32(Bs[n * ROWSTRIDE + k0 + tig + 4]);
            }
#pragma unroll
            for (int mt = 0; mt < 4; mt++)
#pragma unroll
                for (int nt = 0; nt < 4; nt++)
                    mma_tf32(acc[mt][nt], af[mt], bf[nt]);
        }
        __syncthreads();
    }

#pragma unroll
    for (int mt = 0; mt < 4; mt++) {
        int r0 = m0 + warp_m * 64 + mt * 16 + g;
#pragma unroll
        for (int nt = 0; nt < 4; nt++) {
            int c = n0 + warp_n * 32 + nt * 8 + tig * 2;
            float b0 = bias[c];
            float b1 = bias[c + 1];
            float2 v0 = make_float2(acc[mt][nt][0] + b0, acc[mt][nt][1] + b1);
            float2 v1 = make_float2(acc[mt][nt][2] + b0, acc[mt][nt][3] + b1);
            *(float2*)(C + (size_t)r0 * N + c)       = v0;
            *(float2*)(C + (size_t)(r0 + 8) * N + c) = v1;
        }
    }
}

// ---------------------------------------------------------------------------
// Tensor-core window attention: one block (128 thr, 4 warps) per (b, h).
// M=N padded 49->64, K(dhead)=32. QK^T and PV as m16n8k8 tf32 MMAs.
// Softmax in registers with shfl reductions; P staged via smem per-warp.
// ---------------------------------------------------------------------------
#define QS 36   // stride for sQ/sK/sV rows (conflict-free A/B frags)
#define PS 68   // stride for sP rows

__global__ __launch_bounds__(128)
void attn_mma(const float* __restrict__ qkv,
              const float* __restrict__ mask,
              const float* __restrict__ bias_table,
              float* __restrict__ out)
{
    const int b   = blockIdx.x;
    const int h   = blockIdx.y;
    const int tid = threadIdx.x;
    const int wid = tid >> 5;
    const int lane = tid & 31;
    const int g   = lane >> 2;
    const int tig = lane & 3;
    const float scale = 0.17677669529663689f;

    __shared__ float sQ[64][QS];
    __shared__ float sK[64][QS];
    __shared__ float sV[64][QS];
    __shared__ float sP[64][PS];
    __shared__ float sBias[169];

    // ---- load Q (pre-scaled, tf32-rounded), K, V (tf32-rounded); pad rows 0
    for (int idx = tid; idx < 64 * DHEAD; idx += 128) {
        int n = idx >> 5;
        int d = idx & 31;
        float q = 0.f, k = 0.f, v = 0.f;
        if (n < NTOK) {
            const float* base = qkv + (size_t)(b * NTOK + n) * QKVN + h * DHEAD + d;
            q = base[0] * scale;
            k = base[CDIM];
            v = base[2 * CDIM];
        }
        sQ[n][d] = __uint_as_float(f2tf32(q));
        sK[n][d] = __uint_as_float(f2tf32(k));
        sV[n][d] = __uint_as_float(f2tf32(v));
    }
    // FIX: 169 entries, 128 threads -> must stride (R6 bug: entries 128..168
    // were uninitialized garbage)
    for (int i = tid; i < 169; i += 128) sBias[i] = bias_table[i * NHEAD + h];
    __syncthreads();

    const int r0 = wid * 16;                  // warp's row slab
    const float* mrow = mask + (size_t)(b & (NW - 1)) * NTOK * NTOK;

    // ---- S = Q K^T  (64x64x32) ----
    float sacc[8][4];
#pragma unroll
    for (int nt = 0; nt < 8; nt++)
#pragma unroll
        for (int c = 0; c < 4; c++) sacc[nt][c] = 0.f;

#pragma unroll
    for (int ks = 0; ks < 4; ks++) {
        const int k0 = ks * 8;
        uint32_t a[4];
        a[0] = fbits(sQ[r0 + g    ][k0 + tig    ]);
        a[1] = fbits(sQ[r0 + g + 8][k0 + tig    ]);
        a[2] = fbits(sQ[r0 + g    ][k0 + tig + 4]);
        a[3] = fbits(sQ[r0 + g + 8][k0 + tig + 4]);
#pragma unroll
        for (int nt = 0; nt < 8; nt++) {
            uint32_t bb[2];
            bb[0] = fbits(sK[nt * 8 + g][k0 + tig    ]);
            bb[1] = fbits(sK[nt * 8 + g][k0 + tig + 4]);
            mma_tf32(sacc[nt], a, bb);
        }
    }

    // ---- add rel-pos bias + mask; kill padding cols ----
    const int iA = r0 + g;
    const int iB = r0 + g + 8;
    const int yA = iA / 7, xA = iA - yA * 7;
    const int yB = iB / 7, xB = iB - yB * 7;
#pragma unroll
    for (int nt = 0; nt < 8; nt++) {
        const int j0 = nt * 8 + tig * 2;
#pragma unroll
        for (int u = 0; u < 2; u++) {
            int j = j0 + u;
            if (j < NTOK) {
                int yj = j / 7, xj = j - yj * 7;
                if (iA < NTOK) {
                    int rel = (yA - yj + 6) * 13 + (xA - xj + 6);
                    sacc[nt][u] += sBias[rel] + mrow[iA * NTOK + j];
                } else sacc[nt][u] = -1e30f;
                if (iB < NTOK) {
                    int rel = (yB - yj + 6) * 13 + (xB - xj + 6);
                    sacc[nt][u + 2] += sBias[rel] + mrow[iB * NTOK + j];
                } else sacc[nt][u + 2] = -1e30f;
            } else {
                sacc[nt][u]     = -1e30f;
                sacc[nt][u + 2] = -1e30f;
            }
        }
    }

    // ---- softmax over rows iA, iB (each row held by 4 lanes: tig 0..3) ----
    float mA = -1e30f, mB = -1e30f;
#pragma unroll
    for (int nt = 0; nt < 8; nt++) {
        mA = fmaxf(mA, fmaxf(sacc[nt][0], sacc[nt][1]));
        mB = fmaxf(mB, fmaxf(sacc[nt][2], sacc[nt][3]));
    }
    mA = fmaxf(mA, __shfl_xor_sync(0xffffffff, mA, 1));
    mA = fmaxf(mA, __shfl_xor_sync(0xffffffff, mA, 2));
    mB = fmaxf(mB, __shfl_xor_sync(0xffffffff, mB, 1));
    mB = fmaxf(mB, __shfl_xor_sync(0xffffffff, mB, 2));

    float sumA = 0.f, sumB = 0.f;
#pragma unroll
    for (int nt = 0; nt < 8; nt++) {
        sacc[nt][0] = __expf(sacc[nt][0] - mA);
        sacc[nt][1] = __expf(sacc[nt][1] - mA);
        sacc[nt][2] = __expf(sacc[nt][2] - mB);
        sacc[nt][3] = __expf(sacc[nt][3] - mB);
        sumA += sacc[nt][0] + sacc[nt][1];
        sumB += sacc[nt][2] + sacc[nt][3];
    }
    sumA += __shfl_xor_sync(0xffffffff, sumA, 1);
    sumA += __shfl_xor_sync(0xffffffff, sumA, 2);
    sumB += __shfl_xor_sync(0xffffffff, sumB, 1);
    sumB += __shfl_xor_sync(0xffffffff, sumB, 2);
    const float invA = 1.0f / sumA;
    const float invB = 1.0f / sumB;

    // ---- store P (tf32-rounded) to this warp's 16 rows of sP ----
#pragma unroll
    for (int nt = 0; nt < 8; nt++) {
        const int j0 = nt * 8 + tig * 2;
        sP[iA][j0    ] = __uint_as_float(f2tf32(sacc[nt][0] * invA));
        sP[iA][j0 + 1] = __uint_as_float(f2tf32(sacc[nt][1] * invA));
        sP[iB][j0    ] = __uint_as_float(f2tf32(sacc[nt][2] * invB));
        sP[iB][j0 + 1] = __uint_as_float(f2tf32(sacc[nt][3] * invB));
    }
    __syncwarp();   // warp reads back only its own rows

    // ---- O = P V  (64x32x64) ----
    float oacc[4][4];
#pragma unroll
    for (int nt = 0; nt < 4; nt++)
#pragma unroll
        for (int c = 0; c < 4; c++) oacc[nt][c] = 0.f;

#pragma unroll
    for (int ks = 0; ks < 8; ks++) {
        const int k0 = ks * 8;
        uint32_t a[4];
        a[0] = fbits(sP[r0 + g    ][k0 + tig    ]);
        a[1] = fbits(sP[r0 + g + 8][k0 + tig    ]);
        a[2] = fbits(sP[r0 + g    ][k0 + tig + 4]);
        a[3] = fbits(sP[r0 + g + 8][k0 + tig + 4]);
#pragma unroll
        for (int nt = 0; nt < 4; nt++) {
            uint32_t bb[2];
            bb[0] = fbits(sV[k0 + tig    ][nt * 8 + g]);
            bb[1] = fbits(sV[k0 + tig + 4][nt * 8 + g]);
            mma_tf32(oacc[nt], a, bb);
        }
    }

    // ---- write O rows < 49, (b, n, h, d) layout ----
#pragma unroll
    for (int nt = 0; nt < 4; nt++) {
        const int d0 = nt * 8 + tig * 2;
        if (iA < NTOK)
            *(float2*)(out + (size_t)(b * NTOK + iA) * CDIM + h * DHEAD + d0) =
                make_float2(oacc[nt][0], oacc[nt][1]);
        if (iB < NTOK)
            *(float2*)(out + (size_t)(b * NTOK + iB) * CDIM + h * DHEAD + d0) =
                make_float2(oacc[nt][2], oacc[nt][3]);
    }
}

// ---------------------------------------------------------------------------
// Launch
// ---------------------------------------------------------------------------
extern "C" void kernel_launch(void* const* d_in, const int* in_sizes, int n_in,
                              void* d_out, int out_size)
{
    const float* x          = (const float*)d_in[0];
    const float* mask       = (const float*)d_in[1];
    const float* qkv_w      = (const float*)d_in[2];
    const float* qkv_b      = (const float*)d_in[3];
    const float* proj_w     = (const float*)d_in[4];
    const float* proj_b     = (const float*)d_in[5];
    const float* bias_table = (const float*)d_in[6];
    float* out = (float*)d_out;

    float* qkv;
    float* att;
    cudaGetSymbolAddress((void**)&qkv, g_qkv);
    cudaGetSymbolAddress((void**)&att, g_att);

    static bool attr_set = false;
    if (!attr_set) {
        cudaFuncSetAttribute(gemm_tf32_tn_bias,
                             cudaFuncAttributeMaxDynamicSharedMemorySize,
                             SMEM_BYTES);
        attr_set = true;
    }

    // 1) QKV projection
    {
        dim3 grid(QKVN / GBN, MROWS / GBM);
        gemm_tf32_tn_bias<<<grid, 256, SMEM_BYTES>>>(x, qkv_w, qkv_b, qkv,
                                                     MROWS, QKVN, CDIM);
    }

    // 2) Tensor-core windowed attention
    {
        dim3 grid(B_WIN, NHEAD);
        attn_mma<<<grid, 128>>>(qkv, mask, bias_table, att);
    }

    // 3) Output projection
    {
        dim3 grid(CDIM / GBN, MROWS / GBM);
        gemm_tf32_tn_bias<<<grid, 256, SMEM_BYTES>>>(att, proj_w, proj_b, out,
                                                     MROWS, CDIM, CDIM);
    }
}